// round 10
// baseline (speedup 1.0000x reference)
#include <cuda_runtime.h>
#include <cuda_bf16.h>
#include <cstdint>

#define N_NODES 20000
#define N_EDGES 200000
#define FEAT    128
#define NB      8
#define SI      16
#define SO      16
#define NREL    230
#define WROW    (NB*SI*SO)       // 2048 floats per relation
#define NSUB    32               // sub-counters per relation
#define NCNT    (NREL*NSUB)      // 7360
#define EPW     32               // edges per warp
#define NWARPS  (N_EDGES/EPW)    // 6250
#define EDGE_CTAS ((NWARPS + 7) / 8)            // 782
#define MT 64
#define KT 32
#define GEMM_CTAS ((N_NODES + MT - 1) / MT)     // 313

// ---------------- packed f32x2 helpers -----------------------------------------
#define PACK_F32X2(out, lo, hi) \
    asm("mov.b64 %0, {%1, %2};" : "=l"(out) : "f"(lo), "f"(hi))
#define UNPACK_F32X2(lo, hi, in) \
    asm("mov.b64 {%0, %1}, %2;" : "=f"(lo), "=f"(hi) : "l"(in))
#define FMA_F32X2(d, a, b, c) \
    asm("fma.rn.f32x2 %0, %1, %2, %3;" : "=l"(d) : "l"(a), "l"(b), "l"(c))

// ---------------- scratch (device globals) -------------------------------------
__device__ float g_agg[(size_t)N_NODES * FEAT];      // zero at load; re-zeroed by epilogue
__device__ int   g_counts[NCNT];                     // zero at load; re-zeroed by scan
__device__ int   g_cursor[NCNT];
__device__ int   g_rank[N_EDGES];
__device__ int4  g_edge[N_EDGES];                    // sorted {src,dst,type,norm}

// ---------------- K0: histogram with rank (200k threads only) ------------------
__global__ void hist_kernel(const int* __restrict__ etype) {
    int e = blockIdx.x * blockDim.x + threadIdx.x;
    if (e < N_EDGES) {
        int t = etype[e];
        int r = atomicAdd(&g_counts[t * NSUB + (e & (NSUB - 1))], 1);
        g_rank[e] = r;
    }
}

// ---------------- K1: exclusive scan over 7360 counters + reset ----------------
__global__ void __launch_bounds__(1024) scan_kernel() {
    __shared__ int sp[1024];
    int t = threadIdx.x;
    int base = t * 8;
    int v[8];
    int sum = 0;
    #pragma unroll
    for (int i = 0; i < 8; ++i) {
        if (base + i < NCNT) {
            v[i] = g_counts[base + i];
            g_counts[base + i] = 0;          // reset for next graph replay
        } else v[i] = 0;
        sum += v[i];
    }
    sp[t] = sum;
    __syncthreads();
    #pragma unroll
    for (int off = 1; off < 1024; off <<= 1) {
        int x = (t >= off) ? sp[t - off] : 0;
        __syncthreads();
        sp[t] += x;
        __syncthreads();
    }
    int run = sp[t] - sum;
    #pragma unroll
    for (int i = 0; i < 8; ++i) {
        if (base + i < NCNT) g_cursor[base + i] = run;
        run += v[i];
    }
}

// ---------------- K2: atomic-free scatter ----------------------------------------
__global__ void scatter_kernel(const int* __restrict__ etype,
                               const int* __restrict__ esrc,
                               const int* __restrict__ edst,
                               const float* __restrict__ enorm) {
    int e = blockIdx.x * blockDim.x + threadIdx.x;
    if (e < N_EDGES) {
        int t = etype[e];
        int c = t * NSUB + (e & (NSUB - 1));
        int pos = __ldg(&g_cursor[c]) + g_rank[e];
        g_edge[pos] = make_int4(esrc[e], edst[e], t, __float_as_int(enorm[e]));
    }
}

// ---------------- K3: fused self-loop GEMM + edge-message -----------------------
// CTAs [0, GEMM_CTAS): g_agg += (h @ loop_weight) / node_norm  (RED, race-free
//   vs edge REDs since addition is atomic & commutative).
// CTAs [GEMM_CTAS, ...): edge path — k-pair f32x2 weights, zero hot-loop packs.
__global__ void __launch_bounds__(256) fused_kernel(
    const float* __restrict__ h,
    const float* __restrict__ weight,
    const float* __restrict__ loop_weight,
    const float* __restrict__ node_norm)
{
    __shared__ float sW[KT][FEAT];           // GEMM branch only
    __shared__ float sH[MT][KT + 4];

    if (blockIdx.x >= GEMM_CTAS) {
        // ======================= EDGE BRANCH ====================================
        const int warp = (blockIdx.x - GEMM_CTAS) * 8 + (threadIdx.x >> 5);
        if (warp >= NWARPS) return;
        const int lane = threadIdx.x & 31;
        const int e0   = warp * EPW;
        const int b    = lane >> 2;
        const int q    = lane & 3;

        // k-pair weight cache: w{c}[j] = (W[2j][c], W[2j+1][c]) for the lane's
        // 4 channels c = lane*4 .. +3.  64 regs, loaded once per type segment.
        unsigned long long w0[8], w1[8], w2[8], w3[8];
        int cur = -1;

        int4 rec = __ldg(&g_edge[e0]);
        const ulonglong2* hp = reinterpret_cast<const ulonglong2*>(
            h + (size_t)rec.x * FEAT + b * SI);
        ulonglong2 q0 = __ldg(hp + 0);   // (h[k0],h[k1]) pairs: valid f32x2 operands
        ulonglong2 q1 = __ldg(hp + 1);
        ulonglong2 q2 = __ldg(hp + 2);
        ulonglong2 q3 = __ldg(hp + 3);

        #pragma unroll 1
        for (int i = 0; i < EPW; ++i) {
            int4 nrec = rec;
            if (i + 1 < EPW) nrec = __ldg(&g_edge[e0 + i + 1]);

            if (rec.z != cur) {
                cur = rec.z;
                const float* wp = weight + (size_t)cur * WROW + b * (SI * SO) + q * 4;
                #pragma unroll
                for (int j = 0; j < 8; ++j) {
                    float4 ka = __ldg(reinterpret_cast<const float4*>(wp + (2*j)   * SO));
                    float4 kb = __ldg(reinterpret_cast<const float4*>(wp + (2*j+1) * SO));
                    PACK_F32X2(w0[j], ka.x, kb.x);
                    PACK_F32X2(w1[j], ka.y, kb.y);
                    PACK_F32X2(w2[j], ka.z, kb.z);
                    PACK_F32X2(w3[j], ka.w, kb.w);
                }
            }

            unsigned long long a0 = 0ULL, a1 = 0ULL, a2 = 0ULL, a3 = 0ULL;
            #define EK(j, hq) {                          \
                FMA_F32X2(a0, hq, w0[j], a0);            \
                FMA_F32X2(a1, hq, w1[j], a1);            \
                FMA_F32X2(a2, hq, w2[j], a2);            \
                FMA_F32X2(a3, hq, w3[j], a3); }
            EK(0, q0.x) EK(1, q0.y)
            EK(2, q1.x) EK(3, q1.y)
            EK(4, q2.x) EK(5, q2.y)
            EK(6, q3.x) EK(7, q3.y)
            #undef EK

            int   dsti = rec.y;
            float en   = __int_as_float(rec.w);

            // prefetch next edge's h row (a0..a3 carry the live results)
            if (i + 1 < EPW) {
                const ulonglong2* np = reinterpret_cast<const ulonglong2*>(
                    h + (size_t)nrec.x * FEAT + b * SI);
                q0 = __ldg(np + 0);
                q1 = __ldg(np + 1);
                q2 = __ldg(np + 2);
                q3 = __ldg(np + 3);
            }
            rec = nrec;

            // tail: pair-halves are plain registers (unpack MOVs coalesce away)
            float l0, u0, l1, u1, l2, u2, l3, u3;
            UNPACK_F32X2(l0, u0, a0);
            UNPACK_F32X2(l1, u1, a1);
            UNPACK_F32X2(l2, u2, a2);
            UNPACK_F32X2(l3, u3, a3);
            float r0 = (l0 + u0) * en;
            float r1 = (l1 + u1) * en;
            float r2 = (l2 + u2) * en;
            float r3 = (l3 + u3) * en;

            float* dst = g_agg + (size_t)dsti * FEAT + lane * 4;
            asm volatile("red.global.add.v4.f32 [%0], {%1, %2, %3, %4};"
                         :: "l"(dst), "f"(r0), "f"(r1), "f"(r2), "f"(r3)
                         : "memory");
        }
    } else {
        // ======================= GEMM BRANCH: g_agg += (h@W_loop)/nn =============
        const int tid = threadIdx.x;
        const int tm  = tid >> 5;
        const int to  = tid & 31;
        const int n0  = blockIdx.x * MT;

        unsigned long long acc01[8], acc23[8];
        #pragma unroll
        for (int r = 0; r < 8; ++r) { acc01[r] = 0ULL; acc23[r] = 0ULL; }

        for (int kt = 0; kt < FEAT / KT; ++kt) {
            #pragma unroll
            for (int j = 0; j < 4; ++j) {
                int idx = tid + j * 256;
                int r   = idx >> 5;
                int c4  = idx & 31;
                float4 v = __ldg(reinterpret_cast<const float4*>(
                    loop_weight + (size_t)(kt * KT + r) * FEAT + c4 * 4));
                *reinterpret_cast<float4*>(&sW[r][c4 * 4]) = v;
            }
            #pragma unroll
            for (int j = 0; j < 2; ++j) {
                int idx = tid + j * 256;
                int r   = idx >> 3;
                int c4  = idx & 7;
                int n   = n0 + r;
                float4 v = make_float4(0.f, 0.f, 0.f, 0.f);
                if (n < N_NODES)
                    v = __ldg(reinterpret_cast<const float4*>(
                            h + (size_t)n * FEAT + kt * KT + c4 * 4));
                *reinterpret_cast<float4*>(&sH[r][c4 * 4]) = v;
            }
            __syncthreads();

            #pragma unroll
            for (int k = 0; k < KT; k += 4) {
                ulonglong2 wv0 = *reinterpret_cast<const ulonglong2*>(&sW[k + 0][to * 4]);
                ulonglong2 wv1 = *reinterpret_cast<const ulonglong2*>(&sW[k + 1][to * 4]);
                ulonglong2 wv2 = *reinterpret_cast<const ulonglong2*>(&sW[k + 2][to * 4]);
                ulonglong2 wv3 = *reinterpret_cast<const ulonglong2*>(&sW[k + 3][to * 4]);
                #pragma unroll
                for (int r = 0; r < 8; ++r) {
                    float4 hv = *reinterpret_cast<const float4*>(&sH[tm * 8 + r][k]);
                    unsigned long long h2;
                    PACK_F32X2(h2, hv.x, hv.x);
                    FMA_F32X2(acc01[r], h2, wv0.x, acc01[r]);
                    FMA_F32X2(acc23[r], h2, wv0.y, acc23[r]);
                    PACK_F32X2(h2, hv.y, hv.y);
                    FMA_F32X2(acc01[r], h2, wv1.x, acc01[r]);
                    FMA_F32X2(acc23[r], h2, wv1.y, acc23[r]);
                    PACK_F32X2(h2, hv.z, hv.z);
                    FMA_F32X2(acc01[r], h2, wv2.x, acc01[r]);
                    FMA_F32X2(acc23[r], h2, wv2.y, acc23[r]);
                    PACK_F32X2(h2, hv.w, hv.w);
                    FMA_F32X2(acc01[r], h2, wv3.x, acc01[r]);
                    FMA_F32X2(acc23[r], h2, wv3.y, acc23[r]);
                }
            }
            __syncthreads();
        }

        const int o0 = to * 4;
        #pragma unroll
        for (int r = 0; r < 8; ++r) {
            int n = n0 + tm * 8 + r;
            if (n < N_NODES) {
                float rinv = 1.0f / __ldg(&node_norm[n]);   // epilogue re-multiplies by nn
                float a0, a1, a2, a3;
                UNPACK_F32X2(a0, a1, acc01[r]);
                UNPACK_F32X2(a2, a3, acc23[r]);
                a0 *= rinv; a1 *= rinv; a2 *= rinv; a3 *= rinv;
                float* dst = g_agg + (size_t)n * FEAT + o0;
                asm volatile("red.global.add.v4.f32 [%0], {%1, %2, %3, %4};"
                             :: "l"(dst), "f"(a0), "f"(a1), "f"(a2), "f"(a3)
                             : "memory");
            }
        }
    }
}

// ---------------- K4: epilogue + agg reset + time-embedding gather --------------
__global__ void __launch_bounds__(256) epilogue_kernel(
    const float* __restrict__ node_norm,
    const float* __restrict__ h_bias,
    const float* __restrict__ time_embed,
    const int*   __restrict__ time_idx,
    float*       __restrict__ out)
{
    int idx = blockIdx.x * blockDim.x + threadIdx.x;
    const int total = N_NODES * (FEAT / 4);     // 640000
    if (idx >= total) return;
    int n  = idx >> 5;
    int c4 = idx & 31;
    int o0 = c4 * 4;

    float nn  = __ldg(&node_norm[n]);
    float4 hb = __ldg(reinterpret_cast<const float4*>(h_bias + o0));
    float4 ag = *reinterpret_cast<const float4*>(&g_agg[(size_t)n * FEAT + o0]);

    float4 res;
    res.x = fmaxf(ag.x * nn + hb.x, 0.f);
    res.y = fmaxf(ag.y * nn + hb.y, 0.f);
    res.z = fmaxf(ag.z * nn + hb.z, 0.f);
    res.w = fmaxf(ag.w * nn + hb.w, 0.f);
    *reinterpret_cast<float4*>(out + (size_t)n * FEAT + o0) = res;

    // reset agg for the next graph replay (consumed above)
    *reinterpret_cast<float4*>(&g_agg[(size_t)n * FEAT + o0]) =
        make_float4(0.f, 0.f, 0.f, 0.f);

    // time embedding gather
    int ti = __ldg(&time_idx[n]);
    float4 te = __ldg(reinterpret_cast<const float4*>(
        time_embed + (size_t)ti * FEAT + o0));
    *reinterpret_cast<float4*>(out + (size_t)(N_NODES + n) * FEAT + o0) = te;
}

// ---------------- launch ---------------------------------------------------------
extern "C" void kernel_launch(void* const* d_in, const int* in_sizes, int n_in,
                              void* d_out, int out_size) {
    const float* h           = (const float*)d_in[0];
    const float* edge_norm   = (const float*)d_in[1];
    const float* node_norm   = (const float*)d_in[2];
    const float* weight      = (const float*)d_in[3];
    const float* h_bias      = (const float*)d_in[4];
    const float* loop_weight = (const float*)d_in[5];
    const float* time_embed  = (const float*)d_in[6];
    const int*   edge_src    = (const int*)d_in[7];
    const int*   edge_dst    = (const int*)d_in[8];
    const int*   edge_type   = (const int*)d_in[9];
    const int*   time_idx    = (const int*)d_in[10];
    float* out = (float*)d_out;

    hist_kernel<<<(N_EDGES + 255) / 256, 256>>>(edge_type);
    scan_kernel<<<1, 1024>>>();
    scatter_kernel<<<(N_EDGES + 255) / 256, 256>>>(edge_type, edge_src,
                                                   edge_dst, edge_norm);
    fused_kernel<<<GEMM_CTAS + EDGE_CTAS, 256>>>(h, weight, loop_weight,
                                                 node_norm);
    {
        int total = N_NODES * (FEAT / 4);
        epilogue_kernel<<<(total + 255) / 256, 256>>>(
            node_norm, h_bias, time_embed, time_idx, out);
    }
}

// round 11
// speedup vs baseline: 1.1305x; 1.1305x over previous
#include <cuda_runtime.h>
#include <cuda_bf16.h>
#include <cstdint>

#define N_NODES 20000
#define N_EDGES 200000
#define FEAT    128
#define NB      8
#define SI      16
#define SO      16
#define NREL    230
#define WROW    (NB*SI*SO)       // 2048 floats per relation
#define NSUB    32               // sub-counters per relation
#define NCNT    (NREL*NSUB)      // 7360
#define EPW     16               // edges per warp (finer tail granularity)
#define NWARPS  ((N_EDGES + EPW - 1) / EPW)     // 12500
#define EDGE_CTAS ((NWARPS + 7) / 8)            // 1563
#define MT 64
#define KT 32
#define GEMM_CTAS ((N_NODES + MT - 1) / MT)     // 313

// ---------------- packed f32x2 helpers -----------------------------------------
#define PACK_F32X2(out, lo, hi) \
    asm("mov.b64 %0, {%1, %2};" : "=l"(out) : "f"(lo), "f"(hi))
#define UNPACK_F32X2(lo, hi, in) \
    asm("mov.b64 {%0, %1}, %2;" : "=f"(lo), "=f"(hi) : "l"(in))
#define FMA_F32X2(d, a, b, c) \
    asm("fma.rn.f32x2 %0, %1, %2, %3;" : "=l"(d) : "l"(a), "l"(b), "l"(c))

// ---------------- scratch (device globals) -------------------------------------
__device__ float g_agg[(size_t)N_NODES * FEAT];      // 10.24 MB
__device__ float g_loop[(size_t)N_NODES * FEAT];     // 10.24 MB self-loop msg
__device__ int   g_counts[NCNT];                     // zero at load; re-zeroed by scan
__device__ int   g_cursor[NCNT];
__device__ int   g_rank[N_EDGES];
__device__ int4  g_edge[N_EDGES];                    // sorted {src,dst,type,norm}

// ---------------- K0: zero agg + hist-with-rank + time-embedding gather --------
__global__ void front_kernel(const int*   __restrict__ etype,
                             const int*   __restrict__ time_idx,
                             const float* __restrict__ time_embed,
                             float*       __restrict__ out) {
    int i = blockIdx.x * blockDim.x + threadIdx.x;
    const int n4 = N_NODES * FEAT / 4;   // 640000
    if (i < n4) {
        reinterpret_cast<float4*>(g_agg)[i] = make_float4(0.f, 0.f, 0.f, 0.f);
        // time embedding gather: out2[n,:] = time_embed[time_idx[n],:]
        int n  = i >> 5;
        int c4 = i & 31;
        int ti = __ldg(&time_idx[n]);
        float4 te = __ldg(reinterpret_cast<const float4*>(
            time_embed + (size_t)ti * FEAT + c4 * 4));
        *reinterpret_cast<float4*>(
            out + (size_t)(N_NODES + n) * FEAT + c4 * 4) = te;
    }
    if (i < N_EDGES) {
        int t = etype[i];
        int r = atomicAdd(&g_counts[t * NSUB + (i & (NSUB - 1))], 1);
        g_rank[i] = r;
    }
}

// ---------------- K1: exclusive scan over 7360 counters + reset ----------------
__global__ void __launch_bounds__(1024) scan_kernel() {
    __shared__ int sp[1024];
    int t = threadIdx.x;
    int base = t * 8;
    int v[8];
    int sum = 0;
    #pragma unroll
    for (int i = 0; i < 8; ++i) {
        if (base + i < NCNT) {
            v[i] = g_counts[base + i];
            g_counts[base + i] = 0;          // reset for next graph replay
        } else v[i] = 0;
        sum += v[i];
    }
    sp[t] = sum;
    __syncthreads();
    #pragma unroll
    for (int off = 1; off < 1024; off <<= 1) {
        int x = (t >= off) ? sp[t - off] : 0;
        __syncthreads();
        sp[t] += x;
        __syncthreads();
    }
    int run = sp[t] - sum;
    #pragma unroll
    for (int i = 0; i < 8; ++i) {
        if (base + i < NCNT) g_cursor[base + i] = run;
        run += v[i];
    }
}

// ---------------- K2: atomic-free scatter ----------------------------------------
__global__ void scatter_kernel(const int* __restrict__ etype,
                               const int* __restrict__ esrc,
                               const int* __restrict__ edst,
                               const float* __restrict__ enorm) {
    int e = blockIdx.x * blockDim.x + threadIdx.x;
    if (e < N_EDGES) {
        int t = etype[e];
        int c = t * NSUB + (e & (NSUB - 1));
        int pos = __ldg(&g_cursor[c]) + g_rank[e];
        g_edge[pos] = make_int4(esrc[e], edst[e], t, __float_as_int(enorm[e]));
    }
}

// ---------------- K3: fused edge-message + self-loop GEMM ------------------------
// CTAs [0, EDGE_CTAS): edge path (round-4 proven code, duplicate-PACK f32x2).
// CTAs [EDGE_CTAS, EDGE_CTAS+GEMM_CTAS): self-loop GEMM -> g_loop.
__global__ void __launch_bounds__(256) fused_kernel(
    const float* __restrict__ h,
    const float* __restrict__ weight,
    const float* __restrict__ loop_weight)
{
    __shared__ float sW[KT][FEAT];           // used by GEMM branch only
    __shared__ float sH[MT][KT + 4];

    if (blockIdx.x < EDGE_CTAS) {
        // ======================= EDGE BRANCH (round-4 verbatim) ================
        const int warp = blockIdx.x * 8 + (threadIdx.x >> 5);
        if (warp >= NWARPS) return;
        const int lane = threadIdx.x & 31;
        const int e0   = warp * EPW;
        int e1 = e0 + EPW;
        if (e1 > N_EDGES) e1 = N_EDGES;
        const int nE = e1 - e0;
        const int b    = lane >> 2;
        const int q    = lane & 3;

        unsigned long long w01[16], w23[16];
        int cur = -1;

        int4 rec = __ldg(&g_edge[e0]);
        const float4* hp = reinterpret_cast<const float4*>(
            h + (size_t)rec.x * FEAT + b * SI);
        float4 x0 = __ldg(hp + 0);
        float4 x1 = __ldg(hp + 1);
        float4 x2 = __ldg(hp + 2);
        float4 x3 = __ldg(hp + 3);

        #pragma unroll 1
        for (int i = 0; i < nE; ++i) {
            int4 nrec = rec;
            if (i + 1 < nE) nrec = __ldg(&g_edge[e0 + i + 1]);

            if (rec.z != cur) {
                cur = rec.z;
                const char* wbase = reinterpret_cast<const char*>(
                    weight + (size_t)cur * WROW + b * (SI * SO) + q * 4);
                #pragma unroll
                for (int k = 0; k < 16; ++k) {
                    ulonglong2 wv = __ldg(reinterpret_cast<const ulonglong2*>(
                        wbase + k * (SO * 4)));
                    w01[k] = wv.x;
                    w23[k] = wv.y;
                }
            }

            unsigned long long a01 = 0ULL, a23 = 0ULL;
            #define EK(k, val) { unsigned long long _p;              \
                PACK_F32X2(_p, val, val);                             \
                FMA_F32X2(a01, _p, w01[k], a01);                      \
                FMA_F32X2(a23, _p, w23[k], a23); }
            EK(0,x0.x) EK(1,x0.y) EK(2,x0.z) EK(3,x0.w)
            EK(4,x1.x) EK(5,x1.y) EK(6,x1.z) EK(7,x1.w)
            EK(8,x2.x) EK(9,x2.y) EK(10,x2.z) EK(11,x2.w)
            EK(12,x3.x) EK(13,x3.y) EK(14,x3.z) EK(15,x3.w)
            #undef EK

            float en = __int_as_float(rec.w);
            float r0, r1, r2, r3;
            UNPACK_F32X2(r0, r1, a01);
            UNPACK_F32X2(r2, r3, a23);
            r0 *= en; r1 *= en; r2 *= en; r3 *= en;
            float* dst = g_agg + (size_t)rec.y * FEAT + lane * 4;
            asm volatile("red.global.add.v4.f32 [%0], {%1, %2, %3, %4};"
                         :: "l"(dst), "f"(r0), "f"(r1), "f"(r2), "f"(r3)
                         : "memory");

            if (i + 1 < nE) {
                const float4* np = reinterpret_cast<const float4*>(
                    h + (size_t)nrec.x * FEAT + b * SI);
                x0 = __ldg(np + 0);
                x1 = __ldg(np + 1);
                x2 = __ldg(np + 2);
                x3 = __ldg(np + 3);
            }
            rec = nrec;
        }
    } else {
        // ======================= GEMM BRANCH: g_loop = h @ loop_weight ==========
        const int tid = threadIdx.x;
        const int tm  = tid >> 5;
        const int to  = tid & 31;
        const int n0  = (blockIdx.x - EDGE_CTAS) * MT;

        unsigned long long acc01[8], acc23[8];
        #pragma unroll
        for (int r = 0; r < 8; ++r) { acc01[r] = 0ULL; acc23[r] = 0ULL; }

        for (int kt = 0; kt < FEAT / KT; ++kt) {
            #pragma unroll
            for (int j = 0; j < 4; ++j) {
                int idx = tid + j * 256;
                int r   = idx >> 5;
                int c4  = idx & 31;
                float4 v = __ldg(reinterpret_cast<const float4*>(
                    loop_weight + (size_t)(kt * KT + r) * FEAT + c4 * 4));
                *reinterpret_cast<float4*>(&sW[r][c4 * 4]) = v;
            }
            #pragma unroll
            for (int j = 0; j < 2; ++j) {
                int idx = tid + j * 256;
                int r   = idx >> 3;
                int c4  = idx & 7;
                int n   = n0 + r;
                float4 v = make_float4(0.f, 0.f, 0.f, 0.f);
                if (n < N_NODES)
                    v = __ldg(reinterpret_cast<const float4*>(
                            h + (size_t)n * FEAT + kt * KT + c4 * 4));
                *reinterpret_cast<float4*>(&sH[r][c4 * 4]) = v;
            }
            __syncthreads();

            #pragma unroll
            for (int k = 0; k < KT; k += 4) {
                ulonglong2 wv0 = *reinterpret_cast<const ulonglong2*>(&sW[k + 0][to * 4]);
                ulonglong2 wv1 = *reinterpret_cast<const ulonglong2*>(&sW[k + 1][to * 4]);
                ulonglong2 wv2 = *reinterpret_cast<const ulonglong2*>(&sW[k + 2][to * 4]);
                ulonglong2 wv3 = *reinterpret_cast<const ulonglong2*>(&sW[k + 3][to * 4]);
                #pragma unroll
                for (int r = 0; r < 8; ++r) {
                    float4 hv = *reinterpret_cast<const float4*>(&sH[tm * 8 + r][k]);
                    unsigned long long h2;
                    PACK_F32X2(h2, hv.x, hv.x);
                    FMA_F32X2(acc01[r], h2, wv0.x, acc01[r]);
                    FMA_F32X2(acc23[r], h2, wv0.y, acc23[r]);
                    PACK_F32X2(h2, hv.y, hv.y);
                    FMA_F32X2(acc01[r], h2, wv1.x, acc01[r]);
                    FMA_F32X2(acc23[r], h2, wv1.y, acc23[r]);
                    PACK_F32X2(h2, hv.z, hv.z);
                    FMA_F32X2(acc01[r], h2, wv2.x, acc01[r]);
                    FMA_F32X2(acc23[r], h2, wv2.y, acc23[r]);
                    PACK_F32X2(h2, hv.w, hv.w);
                    FMA_F32X2(acc01[r], h2, wv3.x, acc01[r]);
                    FMA_F32X2(acc23[r], h2, wv3.y, acc23[r]);
                }
            }
            __syncthreads();
        }

        const int o0 = to * 4;
        #pragma unroll
        for (int r = 0; r < 8; ++r) {
            int n = n0 + tm * 8 + r;
            if (n < N_NODES) {
                float a0, a1, a2, a3;
                UNPACK_F32X2(a0, a1, acc01[r]);
                UNPACK_F32X2(a2, a3, acc23[r]);
                *reinterpret_cast<float4*>(g_loop + (size_t)n * FEAT + o0) =
                    make_float4(a0, a1, a2, a3);
            }
        }
    }
}

// ---------------- K4: epilogue (out1 only; out2 written by K0) -------------------
__global__ void __launch_bounds__(256) epilogue_kernel(
    const float* __restrict__ node_norm,
    const float* __restrict__ h_bias,
    float*       __restrict__ out)
{
    int idx = blockIdx.x * blockDim.x + threadIdx.x;
    const int total = N_NODES * (FEAT / 4);     // 640000
    if (idx >= total) return;
    int n  = idx >> 5;
    int c4 = idx & 31;
    int o0 = c4 * 4;

    float nn  = __ldg(&node_norm[n]);
    float4 hb = __ldg(reinterpret_cast<const float4*>(h_bias + o0));
    float4 ag = *reinterpret_cast<const float4*>(&g_agg [(size_t)n * FEAT + o0]);
    float4 lp = *reinterpret_cast<const float4*>(&g_loop[(size_t)n * FEAT + o0]);

    float4 res;
    res.x = fmaxf(ag.x * nn + hb.x + lp.x, 0.f);
    res.y = fmaxf(ag.y * nn + hb.y + lp.y, 0.f);
    res.z = fmaxf(ag.z * nn + hb.z + lp.z, 0.f);
    res.w = fmaxf(ag.w * nn + hb.w + lp.w, 0.f);
    *reinterpret_cast<float4*>(out + (size_t)n * FEAT + o0) = res;
}

// ---------------- launch ---------------------------------------------------------
extern "C" void kernel_launch(void* const* d_in, const int* in_sizes, int n_in,
                              void* d_out, int out_size) {
    const float* h           = (const float*)d_in[0];
    const float* edge_norm   = (const float*)d_in[1];
    const float* node_norm   = (const float*)d_in[2];
    const float* weight      = (const float*)d_in[3];
    const float* h_bias      = (const float*)d_in[4];
    const float* loop_weight = (const float*)d_in[5];
    const float* time_embed  = (const float*)d_in[6];
    const int*   edge_src    = (const int*)d_in[7];
    const int*   edge_dst    = (const int*)d_in[8];
    const int*   edge_type   = (const int*)d_in[9];
    const int*   time_idx    = (const int*)d_in[10];
    float* out = (float*)d_out;

    {
        int n4 = N_NODES * FEAT / 4;     // 640000
        front_kernel<<<(n4 + 255) / 256, 256>>>(edge_type, time_idx,
                                                time_embed, out);
    }
    scan_kernel<<<1, 1024>>>();
    scatter_kernel<<<(N_EDGES + 255) / 256, 256>>>(edge_type, edge_src,
                                                   edge_dst, edge_norm);
    fused_kernel<<<EDGE_CTAS + GEMM_CTAS, 256>>>(h, weight, loop_weight);
    {
        int total = N_NODES * (FEAT / 4);
        epilogue_kernel<<<(total + 255) / 256, 256>>>(node_norm, h_bias, out);
    }
}

// round 12
// speedup vs baseline: 1.2493x; 1.1051x over previous
#include <cuda_runtime.h>
#include <cuda_bf16.h>
#include <cstdint>

#define N_NODES 20000
#define N_EDGES 200000
#define FEAT    128
#define NB      8
#define SI      16
#define SO      16
#define NREL    230
#define WROW    (NB*SI*SO)       // 2048 floats per relation
#define NSUB    32               // sub-counters per relation
#define NCNT    (NREL*NSUB)      // 7360
#define EPW     32               // edges per warp (200000/32 = 6250 exact)
#define NWARPS  (N_EDGES/EPW)    // 6250
#define EDGE_CTAS ((NWARPS + 7) / 8)            // 782
#define MT 64
#define KT 32
#define GEMM_CTAS ((N_NODES + MT - 1) / MT)     // 313

// ---------------- packed f32x2 helpers -----------------------------------------
#define PACK_F32X2(out, lo, hi) \
    asm("mov.b64 %0, {%1, %2};" : "=l"(out) : "f"(lo), "f"(hi))
#define UNPACK_F32X2(lo, hi, in) \
    asm("mov.b64 {%0, %1}, %2;" : "=f"(lo), "=f"(hi) : "l"(in))
#define FMA_F32X2(d, a, b, c) \
    asm("fma.rn.f32x2 %0, %1, %2, %3;" : "=l"(d) : "l"(a), "l"(b), "l"(c))

// ---------------- cp.async helpers ----------------------------------------------
#define CP_ASYNC16(saddr, gptr) \
    asm volatile("cp.async.ca.shared.global [%0], [%1], 16;" \
                 :: "r"(saddr), "l"(gptr) : "memory")
#define CP_COMMIT() asm volatile("cp.async.commit_group;" ::: "memory")
#define CP_WAIT0()  asm volatile("cp.async.wait_group 0;" ::: "memory")
#define CP_WAIT3()  asm volatile("cp.async.wait_group 3;" ::: "memory")

__device__ __forceinline__ uint32_t s2u(const void* p) {
    return (uint32_t)__cvta_generic_to_shared(p);
}

// ---------------- scratch (device globals) -------------------------------------
__device__ float g_agg[(size_t)N_NODES * FEAT];      // 10.24 MB
__device__ float g_loop[(size_t)N_NODES * FEAT];     // 10.24 MB self-loop msg
__device__ int   g_counts[NCNT];                     // zero at load; re-zeroed by scan
__device__ int   g_cursor[NCNT];
__device__ int4  g_edge[N_EDGES];                    // sorted {src,dst,type,norm}

// ---------------- K0: zero agg + histogram (round-8 exact) ---------------------
__global__ void zero_hist_kernel(const int* __restrict__ etype) {
    int i = blockIdx.x * blockDim.x + threadIdx.x;
    const int n4 = N_NODES * FEAT / 4;   // 640000
    if (i < n4) reinterpret_cast<float4*>(g_agg)[i] =
        make_float4(0.f, 0.f, 0.f, 0.f);
    if (i < N_EDGES)
        atomicAdd(&g_counts[etype[i] * NSUB + (i & (NSUB - 1))], 1);
}

// ---------------- K1: exclusive scan over 7360 counters + reset ----------------
__global__ void __launch_bounds__(1024) scan_kernel() {
    __shared__ int sp[1024];
    int t = threadIdx.x;
    int base = t * 8;
    int v[8];
    int sum = 0;
    #pragma unroll
    for (int i = 0; i < 8; ++i) {
        if (base + i < NCNT) {
            v[i] = g_counts[base + i];
            g_counts[base + i] = 0;          // reset for next graph replay
        } else v[i] = 0;
        sum += v[i];
    }
    sp[t] = sum;
    __syncthreads();
    #pragma unroll
    for (int off = 1; off < 1024; off <<= 1) {
        int x = (t >= off) ? sp[t - off] : 0;
        __syncthreads();
        sp[t] += x;
        __syncthreads();
    }
    int run = sp[t] - sum;
    #pragma unroll
    for (int i = 0; i < 8; ++i) {
        if (base + i < NCNT) g_cursor[base + i] = run;
        run += v[i];
    }
}

// ---------------- K2: scatter (round-8 exact) ------------------------------------
__global__ void scatter_kernel(const int* __restrict__ etype,
                               const int* __restrict__ esrc,
                               const int* __restrict__ edst,
                               const float* __restrict__ enorm) {
    int e = blockIdx.x * blockDim.x + threadIdx.x;
    if (e < N_EDGES) {
        int t = etype[e];
        int c = t * NSUB + (e & (NSUB - 1));
        int pos = atomicAdd(&g_cursor[c], 1);
        g_edge[pos] = make_int4(esrc[e], edst[e], t, __float_as_int(enorm[e]));
    }
}

// ---------------- K3: fused edge-message (cp.async pipeline) + self-loop GEMM ---
// CTAs [0, EDGE_CTAS): edge path. Per-warp smem ring: 32 staged records + 4-deep
//   h-row pipeline filled by cp.async -> zero register cost for prefetch; LDG
//   latency covered by 4 in-flight stages. Compute = round-4 proven FMA chain.
// CTAs [EDGE_CTAS, ...): self-loop GEMM -> g_loop (round-8 verbatim).
__global__ void __launch_bounds__(256) fused_kernel(
    const float* __restrict__ h,
    const float* __restrict__ weight,
    const float* __restrict__ loop_weight)
{
    __shared__ __align__(16) union SMem {
        struct { float W[KT][FEAT]; float H[MT][KT + 4]; } g;   // 25.6 KB
        struct { int4 rec[8][32]; float4 hbuf[8][4][32]; } e;   // 20.5 KB
    } sm;

    if (blockIdx.x < EDGE_CTAS) {
        // ======================= EDGE BRANCH ====================================
        const int w    = threadIdx.x >> 5;
        const int warp = blockIdx.x * 8 + w;
        if (warp >= NWARPS) return;
        const int lane = threadIdx.x & 31;
        const int e0   = warp * EPW;
        const int b    = lane >> 2;
        const int q    = lane & 3;

        int4*   srec = sm.e.rec[w];

        // stage all 32 edge records for this warp (one 16B cp.async per lane)
        CP_ASYNC16(s2u(&srec[lane]), &g_edge[e0 + lane]);
        CP_COMMIT();
        CP_WAIT0();
        __syncwarp();

        // prime 4 h-row stages (each lane copies its 16B slice of the row)
        #pragma unroll
        for (int s = 0; s < 4; ++s) {
            int src = srec[s].x;                     // LDS broadcast
            CP_ASYNC16(s2u(&sm.e.hbuf[w][s][lane]),
                       h + (size_t)src * FEAT + lane * 4);
            CP_COMMIT();
        }

        unsigned long long w01[16], w23[16];
        int cur = -1;

        #pragma unroll 1
        for (int i = 0; i < EPW; ++i) {
            CP_WAIT3();                  // stage i complete (groups retire in order)
            __syncwarp();                // its smem writes visible warp-wide

            int4 rec = srec[i];          // LDS.128 broadcast

            if (rec.z != cur) {
                cur = rec.z;
                const char* wbase = reinterpret_cast<const char*>(
                    weight + (size_t)cur * WROW + b * (SI * SO) + q * 4);
                #pragma unroll
                for (int k = 0; k < 16; ++k) {
                    ulonglong2 wv = __ldg(reinterpret_cast<const ulonglong2*>(
                        wbase + k * (SO * 4)));
                    w01[k] = wv.x;
                    w23[k] = wv.y;
                }
            }

            const float4* hb = sm.e.hbuf[w][i & 3];
            float4 x0 = hb[b * 4 + 0];
            float4 x1 = hb[b * 4 + 1];
            float4 x2 = hb[b * 4 + 2];
            float4 x3 = hb[b * 4 + 3];

            unsigned long long a01 = 0ULL, a23 = 0ULL;
            #define EK(k, val) { unsigned long long _p;              \
                PACK_F32X2(_p, val, val);                             \
                FMA_F32X2(a01, _p, w01[k], a01);                      \
                FMA_F32X2(a23, _p, w23[k], a23); }
            EK(0,x0.x) EK(1,x0.y) EK(2,x0.z) EK(3,x0.w)
            EK(4,x1.x) EK(5,x1.y) EK(6,x1.z) EK(7,x1.w)
            EK(8,x2.x) EK(9,x2.y) EK(10,x2.z) EK(11,x2.w)
            EK(12,x3.x) EK(13,x3.y) EK(14,x3.z) EK(15,x3.w)
            #undef EK

            float en = __int_as_float(rec.w);
            float r0, r1, r2, r3;
            UNPACK_F32X2(r0, r1, a01);
            UNPACK_F32X2(r2, r3, a23);
            r0 *= en; r1 *= en; r2 *= en; r3 *= en;
            float* dst = g_agg + (size_t)rec.y * FEAT + lane * 4;
            asm volatile("red.global.add.v4.f32 [%0], {%1, %2, %3, %4};"
                         :: "l"(dst), "f"(r0), "f"(r1), "f"(r2), "f"(r3)
                         : "memory");

            __syncwarp();                // all lanes consumed stage i&3 buffer
            if (i + 4 < EPW) {
                int nsrc = srec[i + 4].x;
                CP_ASYNC16(s2u(&sm.e.hbuf[w][(i + 4) & 3][lane]),
                           h + (size_t)nsrc * FEAT + lane * 4);
            }
            CP_COMMIT();                 // commit every iter (group order = stage order)
        }
    } else {
        // ======================= GEMM BRANCH: g_loop = h @ loop_weight ==========
        const int tid = threadIdx.x;
        const int tm  = tid >> 5;
        const int to  = tid & 31;
        const int n0  = (blockIdx.x - EDGE_CTAS) * MT;

        unsigned long long acc01[8], acc23[8];
        #pragma unroll
        for (int r = 0; r < 8; ++r) { acc01[r] = 0ULL; acc23[r] = 0ULL; }

        for (int kt = 0; kt < FEAT / KT; ++kt) {
            #pragma unroll
            for (int j = 0; j < 4; ++j) {
                int idx = tid + j * 256;
                int r   = idx >> 5;
                int c4  = idx & 31;
                float4 v = __ldg(reinterpret_cast<const float4*>(
                    loop_weight + (size_t)(kt * KT + r) * FEAT + c4 * 4));
                *reinterpret_cast<float4*>(&sm.g.W[r][c4 * 4]) = v;
            }
            #pragma unroll
            for (int j = 0; j < 2; ++j) {
                int idx = tid + j * 256;
                int r   = idx >> 3;
                int c4  = idx & 7;
                int n   = n0 + r;
                float4 v = make_float4(0.f, 0.f, 0.f, 0.f);
                if (n < N_NODES)
                    v = __ldg(reinterpret_cast<const float4*>(
                            h + (size_t)n * FEAT + kt * KT + c4 * 4));
                *reinterpret_cast<float4*>(&sm.g.H[r][c4 * 4]) = v;
            }
            __syncthreads();

            #pragma unroll
            for (int k = 0; k < KT; k += 4) {
                ulonglong2 wv0 = *reinterpret_cast<const ulonglong2*>(&sm.g.W[k + 0][to * 4]);
                ulonglong2 wv1 = *reinterpret_cast<const ulonglong2*>(&sm.g.W[k + 1][to * 4]);
                ulonglong2 wv2 = *reinterpret_cast<const ulonglong2*>(&sm.g.W[k + 2][to * 4]);
                ulonglong2 wv3 = *reinterpret_cast<const ulonglong2*>(&sm.g.W[k + 3][to * 4]);
                #pragma unroll
                for (int r = 0; r < 8; ++r) {
                    float4 hv = *reinterpret_cast<const float4*>(&sm.g.H[tm * 8 + r][k]);
                    unsigned long long h2;
                    PACK_F32X2(h2, hv.x, hv.x);
                    FMA_F32X2(acc01[r], h2, wv0.x, acc01[r]);
                    FMA_F32X2(acc23[r], h2, wv0.y, acc23[r]);
                    PACK_F32X2(h2, hv.y, hv.y);
                    FMA_F32X2(acc01[r], h2, wv1.x, acc01[r]);
                    FMA_F32X2(acc23[r], h2, wv1.y, acc23[r]);
                    PACK_F32X2(h2, hv.z, hv.z);
                    FMA_F32X2(acc01[r], h2, wv2.x, acc01[r]);
                    FMA_F32X2(acc23[r], h2, wv2.y, acc23[r]);
                    PACK_F32X2(h2, hv.w, hv.w);
                    FMA_F32X2(acc01[r], h2, wv3.x, acc01[r]);
                    FMA_F32X2(acc23[r], h2, wv3.y, acc23[r]);
                }
            }
            __syncthreads();
        }

        const int o0 = to * 4;
        #pragma unroll
        for (int r = 0; r < 8; ++r) {
            int n = n0 + tm * 8 + r;
            if (n < N_NODES) {
                float a0, a1, a2, a3;
                UNPACK_F32X2(a0, a1, acc01[r]);
                UNPACK_F32X2(a2, a3, acc23[r]);
                *reinterpret_cast<float4*>(g_loop + (size_t)n * FEAT + o0) =
                    make_float4(a0, a1, a2, a3);
            }
        }
    }
}

// ---------------- K4: epilogue + time-embedding (round-8 exact) ------------------
__global__ void __launch_bounds__(256) epilogue_kernel(
    const float* __restrict__ node_norm,
    const float* __restrict__ h_bias,
    const float* __restrict__ time_embed,
    const int*   __restrict__ time_idx,
    float*       __restrict__ out)
{
    int idx = blockIdx.x * blockDim.x + threadIdx.x;
    const int total = N_NODES * (FEAT / 4);     // 640000
    if (idx >= total) return;
    int n  = idx >> 5;
    int c4 = idx & 31;
    int o0 = c4 * 4;

    float nn  = __ldg(&node_norm[n]);
    float4 hb = __ldg(reinterpret_cast<const float4*>(h_bias + o0));
    float4 ag = *reinterpret_cast<const float4*>(&g_agg [(size_t)n * FEAT + o0]);
    float4 lp = *reinterpret_cast<const float4*>(&g_loop[(size_t)n * FEAT + o0]);

    float4 res;
    res.x = fmaxf(ag.x * nn + hb.x + lp.x, 0.f);
    res.y = fmaxf(ag.y * nn + hb.y + lp.y, 0.f);
    res.z = fmaxf(ag.z * nn + hb.z + lp.z, 0.f);
    res.w = fmaxf(ag.w * nn + hb.w + lp.w, 0.f);
    *reinterpret_cast<float4*>(out + (size_t)n * FEAT + o0) = res;

    int ti = __ldg(&time_idx[n]);
    float4 te = __ldg(reinterpret_cast<const float4*>(
        time_embed + (size_t)ti * FEAT + o0));
    *reinterpret_cast<float4*>(out + (size_t)(N_NODES + n) * FEAT + o0) = te;
}

// ---------------- launch ---------------------------------------------------------
extern "C" void kernel_launch(void* const* d_in, const int* in_sizes, int n_in,
                              void* d_out, int out_size) {
    const float* h           = (const float*)d_in[0];
    const float* edge_norm   = (const float*)d_in[1];
    const float* node_norm   = (const float*)d_in[2];
    const float* weight      = (const float*)d_in[3];
    const float* h_bias      = (const float*)d_in[4];
    const float* loop_weight = (const float*)d_in[5];
    const float* time_embed  = (const float*)d_in[6];
    const int*   edge_src    = (const int*)d_in[7];
    const int*   edge_dst    = (const int*)d_in[8];
    const int*   edge_type   = (const int*)d_in[9];
    const int*   time_idx    = (const int*)d_in[10];
    float* out = (float*)d_out;

    {
        int n4 = N_NODES * FEAT / 4;
        zero_hist_kernel<<<(n4 + 255) / 256, 256>>>(edge_type);
    }
    scan_kernel<<<1, 1024>>>();
    scatter_kernel<<<(N_EDGES + 255) / 256, 256>>>(edge_type, edge_src,
                                                   edge_dst, edge_norm);
    fused_kernel<<<EDGE_CTAS + GEMM_CTAS, 256>>>(h, weight, loop_weight);
    {
        int total = N_NODES * (FEAT / 4);
        epilogue_kernel<<<(total + 255) / 256, 256>>>(
            node_norm, h_bias, time_embed, time_idx, out);
    }
}